// round 4
// baseline (speedup 1.0000x reference)
#include <cuda_runtime.h>
#include <cuda_bf16.h>
#include <cstdint>

#define D_DIM   50257
#define B_Q     64
#define K_A     4096
#define NPAIR   25129            // ceil(D/2); last pair has only .x valid
#define DSPLIT  18
#define PCHUNK  1397             // ceil(NPAIR/18)
#define KT      256
#define DP      8                // d-pairs per stage (16 d values)
#define EPSF    1e-10f
#define LN2F    0.69314718055994530942f
#define KNN     8

// ---- static device scratch (no cudaMalloc allowed) ----
__device__ float2 g_qlogP[NPAIR * B_Q];           // ~12.9 MB  (pair-major, b fast)
__device__ float  g_cross[DSPLIT * B_Q * K_A];    // ~18.9 MB  partial cross sums (ln units)
__device__ float  g_self [DSPLIT * K_A];          //  partial self sums (ln units)

// ---------------- Kernel A: qlogP[p][b] = (ln(q[b][2p]+eps), ln(q[b][2p+1]+eps)) ----------------
__global__ void qlog_kernel(const float* __restrict__ q) {
    int idx = blockIdx.x * blockDim.x + threadIdx.x;
    if (idx >= B_Q * NPAIR) return;
    int b = idx / NPAIR;
    int p = idx % NPAIR;
    int d0 = 2 * p;
    float2 r;
    float x = q[(size_t)b * D_DIM + d0];
    r.x = __log2f(x + EPSF) * LN2F;
    r.y = 0.f;
    if (d0 + 1 < D_DIM) {
        float y = q[(size_t)b * D_DIM + d0 + 1];
        r.y = __log2f(y + EPSF) * LN2F;
    }
    g_qlogP[p * B_Q + b] = r;
}

// ---------------- Kernel B: fused cross-GEMM + self-term, scalar fp32 FMA ----------------
__global__ void __launch_bounds__(256, 1)
gemm_kernel(const float* __restrict__ anchor) {
    __shared__ __align__(16) float2 As[2][DP][KT];   // 32 KB  (d-pair, local k)
    __shared__ __align__(16) float2 Qs[2][DP][B_Q];  //  8 KB  (d-pair, b)

    const int tid = threadIdx.x;
    const int kb  = blockIdx.x * KT;
    const int c   = blockIdx.y;
    const int pstart = c * PCHUNK;
    const int pend   = min(pstart + PCHUNK, NPAIR);
    const int nst    = (pend - pstart + DP - 1) / DP;

    const int tx = tid & 31;          // k-lane: this thread's k elements are tx + 32*j
    const int ty = tid >> 5;          // warp id -> b group
    const int b0 = ty * 8;

    const int row = kb + tid;         // loader mapping: one anchor row per thread
    const float* __restrict__ arow = anchor + (size_t)row * D_DIM;

    const int qdp = tid >> 6;         // 0..3 ; loads d-pairs qdp and qdp+4
    const int qb  = tid & 63;

    float2 acc[8][8];                 // even-d / odd-d split accumulator chains
#pragma unroll
    for (int i = 0; i < 8; ++i)
#pragma unroll
        for (int j = 0; j < 8; ++j) acc[i][j] = make_float2(0.f, 0.f);

    float2 selfAcc = make_float2(0.f, 0.f);
    float2 va[8];
    float2 qv0, qv1;

    auto loadStage = [&](int s) {
        const int p0 = pstart + s * DP;
        const float* ap = arow + 2 * p0;
#pragma unroll
        for (int j = 0; j < 8; ++j) {
            const int pg = p0 + j;
            float x = 0.f, y = 0.f;
            if (pg < pend) {
                x = __ldg(ap + 2 * j);
                if (2 * pg + 1 < D_DIM) y = __ldg(ap + 2 * j + 1);
            }
            va[j] = make_float2(x, y);
        }
        qv0 = (p0 + qdp     < pend) ? g_qlogP[(p0 + qdp    ) * B_Q + qb] : make_float2(0.f, 0.f);
        qv1 = (p0 + qdp + 4 < pend) ? g_qlogP[(p0 + qdp + 4) * B_Q + qb] : make_float2(0.f, 0.f);
    };

    auto storeStage = [&](int nb) {
#pragma unroll
        for (int j = 0; j < 8; ++j) {
            // self term: a * ln(a+eps); padded zeros contribute exactly 0
            selfAcc.x += va[j].x * __log2f(va[j].x + EPSF);
            selfAcc.y += va[j].y * __log2f(va[j].y + EPSF);
            As[nb][j][tid] = va[j];
        }
        Qs[nb][qdp    ][qb] = qv0;
        Qs[nb][qdp + 4][qb] = qv1;
    };

    loadStage(0);
    storeStage(0);
    __syncthreads();

    int buf = 0;
    for (int s = 0; s < nst; ++s) {
        const bool more = (s + 1 < nst);
        if (more) loadStage(s + 1);   // next-stage global loads in flight across FMA section

#pragma unroll 2
        for (int dp = 0; dp < DP; ++dp) {
            float2 qf[8], af[8];
            const float4* qp = reinterpret_cast<const float4*>(&Qs[buf][dp][b0]); // warp-uniform bcast
#pragma unroll
            for (int h = 0; h < 4; ++h) {
                float4 t = qp[h];
                qf[2 * h]     = make_float2(t.x, t.y);
                qf[2 * h + 1] = make_float2(t.z, t.w);
            }
#pragma unroll
            for (int j = 0; j < 8; ++j)
                af[j] = As[buf][dp][tx + 32 * j];  // lanes consecutive: conflict-free LDS.64
#pragma unroll
            for (int i = 0; i < 8; ++i)
#pragma unroll
                for (int j = 0; j < 8; ++j) {
                    acc[i][j].x = fmaf(qf[i].x, af[j].x, acc[i][j].x);
                    acc[i][j].y = fmaf(qf[i].y, af[j].y, acc[i][j].y);
                }
        }

        if (more) storeStage(buf ^ 1);
        __syncthreads();
        buf ^= 1;
    }

    // ---- epilogue ----
    g_self[c * K_A + row] = (selfAcc.x + selfAcc.y) * LN2F;
#pragma unroll
    for (int i = 0; i < 8; ++i) {
        float* dst = g_cross + ((size_t)(c * B_Q + b0 + i)) * K_A + kb;
#pragma unroll
        for (int j = 0; j < 8; ++j)
            dst[tx + 32 * j] = acc[i][j].x + acc[i][j].y;  // lanes consecutive: coalesced
    }
}

// ---------------- Kernel C: fp64 combine + top-8 argmin + majority vote ----------------
__global__ void __launch_bounds__(256)
topk_kernel(const int* __restrict__ label, float* __restrict__ out) {
    __shared__ double kl[K_A];     // 32 KB
    __shared__ double rv[256];
    __shared__ int    ri[256];
    const int b   = blockIdx.x;
    const int tid = threadIdx.x;

    for (int k = tid; k < K_A; k += 256) {
        double s = 0.0;
#pragma unroll
        for (int c = 0; c < DSPLIT; ++c)
            s += (double)g_self[c * K_A + k]
               - (double)g_cross[((size_t)(c * B_Q + b)) * K_A + k];
        kl[k] = s;   // = D * kl[b][k]; positive scaling is rank-invariant
    }
    __syncthreads();

    int cnt1 = 0;
    for (int r = 0; r < KNN; ++r) {
        double bv = 1e300; int bi = K_A - 1;
        for (int k = tid; k < K_A; k += 256) {
            double v = kl[k];
            if (v < bv) { bv = v; bi = k; }   // ascending k: lowest index wins ties (top_k semantics)
        }
        rv[tid] = bv; ri[tid] = bi;
        __syncthreads();
        for (int off = 128; off > 0; off >>= 1) {
            if (tid < off) {
                double v = rv[tid + off]; int i2 = ri[tid + off];
                if (v < rv[tid] || (v == rv[tid] && i2 < ri[tid])) { rv[tid] = v; ri[tid] = i2; }
            }
            __syncthreads();
        }
        int sel = ri[0];
        if (sel < 0)    sel = 0;
        if (sel >= K_A) sel = K_A - 1;
        cnt1 += label[sel];
        if (tid == 0) kl[sel] = 1e300;
        __syncthreads();
    }
    // knn_cnt = [8-cnt1, cnt1]; argmax ties (4-4) -> class 0
    // *** output written as FLOAT32 — dtype-mismatch hypothesis from rounds 2-3 ***
    if (tid == 0) out[b] = (cnt1 > KNN / 2) ? 1.0f : 0.0f;
}

extern "C" void kernel_launch(void* const* d_in, const int* in_sizes, int n_in,
                              void* d_out, int out_size) {
    (void)in_sizes; (void)n_in; (void)out_size;
    const float* query  = (const float*)d_in[0];
    const float* anchor = (const float*)d_in[1];
    const int*   label  = (const int*)d_in[2];
    float* out = (float*)d_out;

    qlog_kernel<<<(B_Q * NPAIR + 255) / 256, 256>>>(query);
    dim3 g(K_A / KT, DSPLIT);
    gemm_kernel<<<g, 256>>>(anchor);
    topk_kernel<<<B_Q, 256>>>(label, out);
}

// round 5
// speedup vs baseline: 1.0134x; 1.0134x over previous
#include <cuda_runtime.h>
#include <cuda_bf16.h>
#include <cstdint>

#define D_DIM   50257
#define B_Q     64
#define K_A     4096
#define NPAIR   25129            // ceil(D/2); last pair has only .x valid
#define DSPLIT  18
#define PCHUNK  1397             // ceil(NPAIR/18)
#define KT      256
#define DP      8                // d-pairs per stage (16 d values)
#define EPSF    1e-10f
#define LN2F    0.69314718055994530942f
#define KNN     8

// ---- static device scratch (no cudaMalloc allowed) ----
__device__ float2 g_qlogP[NPAIR * B_Q];           // ~12.9 MB  (pair-major, b fast)
__device__ float  g_cross[DSPLIT * B_Q * K_A];    // ~18.9 MB  partial cross sums (ln units)
__device__ float  g_self [DSPLIT * K_A];          //  partial self sums (ln units)

// Packed dual-fp32 FMA (Blackwell f32x2 pipe): d = a*b + c on both lanes.
__device__ __forceinline__ float2 ffma2(float2 a, float2 b, float2 c) {
    unsigned long long ra = *reinterpret_cast<unsigned long long*>(&a);
    unsigned long long rb = *reinterpret_cast<unsigned long long*>(&b);
    unsigned long long rc = *reinterpret_cast<unsigned long long*>(&c);
    unsigned long long rd;
    asm("fma.rn.f32x2 %0, %1, %2, %3;" : "=l"(rd) : "l"(ra), "l"(rb), "l"(rc));
    return *reinterpret_cast<float2*>(&rd);
}

// ---------------- Kernel A: qlogP[p][b] = (ln(q[b][2p]+eps), ln(q[b][2p+1]+eps)) ----------------
__global__ void qlog_kernel(const float* __restrict__ q) {
    int idx = blockIdx.x * blockDim.x + threadIdx.x;
    if (idx >= B_Q * NPAIR) return;
    int b = idx / NPAIR;
    int p = idx % NPAIR;
    int d0 = 2 * p;
    float2 r;
    float x = q[(size_t)b * D_DIM + d0];
    r.x = __log2f(x + EPSF) * LN2F;
    r.y = 0.f;
    if (d0 + 1 < D_DIM) {
        float y = q[(size_t)b * D_DIM + d0 + 1];
        r.y = __log2f(y + EPSF) * LN2F;
    }
    g_qlogP[p * B_Q + b] = r;
}

// ---------------- Kernel B: fused cross-GEMM + self-term, packed f32x2 FMA ----------------
__global__ void __launch_bounds__(256, 1)
gemm_kernel(const float* __restrict__ anchor) {
    __shared__ __align__(16) float2 As[2][DP][KT];   // 32 KB  (d-pair, local k)
    __shared__ __align__(16) float2 Qs[2][DP][B_Q];  //  8 KB  (d-pair, b)

    const int tid = threadIdx.x;
    const int kb  = blockIdx.x * KT;
    const int c   = blockIdx.y;
    const int pstart = c * PCHUNK;
    const int pend   = min(pstart + PCHUNK, NPAIR);
    const int nst    = (pend - pstart + DP - 1) / DP;

    const int tx = tid & 31;          // k-lane: this thread's k elements are tx + 32*j
    const int ty = tid >> 5;          // warp id -> b group
    const int b0 = ty * 8;

    const int row = kb + tid;         // loader mapping: one anchor row per thread
    const float* __restrict__ arow = anchor + (size_t)row * D_DIM;

    const int qdp = tid >> 6;         // 0..3 ; loads d-pairs qdp and qdp+4
    const int qb  = tid & 63;

    float2 acc[8][8];                 // even-d / odd-d split accumulator chains
#pragma unroll
    for (int i = 0; i < 8; ++i)
#pragma unroll
        for (int j = 0; j < 8; ++j) acc[i][j] = make_float2(0.f, 0.f);

    float2 selfAcc = make_float2(0.f, 0.f);
    float2 va[8];
    float2 qv0, qv1;

    auto loadStage = [&](int s) {
        const int p0 = pstart + s * DP;
        const float* ap = arow + 2 * p0;
#pragma unroll
        for (int j = 0; j < 8; ++j) {
            const int pg = p0 + j;
            float x = 0.f, y = 0.f;
            if (pg < pend) {
                x = __ldg(ap + 2 * j);
                if (2 * pg + 1 < D_DIM) y = __ldg(ap + 2 * j + 1);
            }
            va[j] = make_float2(x, y);
        }
        qv0 = (p0 + qdp     < pend) ? g_qlogP[(p0 + qdp    ) * B_Q + qb] : make_float2(0.f, 0.f);
        qv1 = (p0 + qdp + 4 < pend) ? g_qlogP[(p0 + qdp + 4) * B_Q + qb] : make_float2(0.f, 0.f);
    };

    auto storeStage = [&](int nb) {
#pragma unroll
        for (int j = 0; j < 8; ++j) {
            // self term: a * ln(a+eps); padded zeros contribute exactly 0
            selfAcc.x += va[j].x * __log2f(va[j].x + EPSF);
            selfAcc.y += va[j].y * __log2f(va[j].y + EPSF);
            As[nb][j][tid] = va[j];
        }
        Qs[nb][qdp    ][qb] = qv0;
        Qs[nb][qdp + 4][qb] = qv1;
    };

    loadStage(0);
    storeStage(0);
    __syncthreads();

    int buf = 0;
    for (int s = 0; s < nst; ++s) {
        const bool more = (s + 1 < nst);
        if (more) loadStage(s + 1);   // next-stage global loads in flight across FMA section

#pragma unroll 2
        for (int dp = 0; dp < DP; ++dp) {
            float2 qf[8], af[8];
            const float4* qp = reinterpret_cast<const float4*>(&Qs[buf][dp][b0]); // warp-uniform bcast
#pragma unroll
            for (int h = 0; h < 4; ++h) {
                float4 t = qp[h];
                qf[2 * h]     = make_float2(t.x, t.y);
                qf[2 * h + 1] = make_float2(t.z, t.w);
            }
#pragma unroll
            for (int j = 0; j < 8; ++j)
                af[j] = As[buf][dp][tx + 32 * j];  // lanes consecutive: conflict-free LDS.64
#pragma unroll
            for (int i = 0; i < 8; ++i)
#pragma unroll
                for (int j = 0; j < 8; ++j)
                    acc[i][j] = ffma2(qf[i], af[j], acc[i][j]);   // 2 d-steps per instr
        }

        if (more) storeStage(buf ^ 1);
        __syncthreads();
        buf ^= 1;
    }

    // ---- epilogue ----
    g_self[c * K_A + row] = (selfAcc.x + selfAcc.y) * LN2F;
#pragma unroll
    for (int i = 0; i < 8; ++i) {
        float* dst = g_cross + ((size_t)(c * B_Q + b0 + i)) * K_A + kb;
#pragma unroll
        for (int j = 0; j < 8; ++j)
            dst[tx + 32 * j] = acc[i][j].x + acc[i][j].y;  // lanes consecutive: coalesced
    }
}

// ---------------- Kernel C: fp64 combine + top-8 argmin + majority vote ----------------
__global__ void __launch_bounds__(256)
topk_kernel(const int* __restrict__ label, float* __restrict__ out) {
    __shared__ double kl[K_A];     // 32 KB
    __shared__ double rv[256];
    __shared__ int    ri[256];
    const int b   = blockIdx.x;
    const int tid = threadIdx.x;

    for (int k = tid; k < K_A; k += 256) {
        double s = 0.0;
#pragma unroll
        for (int c = 0; c < DSPLIT; ++c)
            s += (double)g_self[c * K_A + k]
               - (double)g_cross[((size_t)(c * B_Q + b)) * K_A + k];
        kl[k] = s;   // = D * kl[b][k]; positive scaling is rank-invariant
    }
    __syncthreads();

    int cnt1 = 0;
    for (int r = 0; r < KNN; ++r) {
        double bv = 1e300; int bi = K_A - 1;
        for (int k = tid; k < K_A; k += 256) {
            double v = kl[k];
            if (v < bv) { bv = v; bi = k; }   // ascending k: lowest index wins ties (top_k semantics)
        }
        rv[tid] = bv; ri[tid] = bi;
        __syncthreads();
        for (int off = 128; off > 0; off >>= 1) {
            if (tid < off) {
                double v = rv[tid + off]; int i2 = ri[tid + off];
                if (v < rv[tid] || (v == rv[tid] && i2 < ri[tid])) { rv[tid] = v; ri[tid] = i2; }
            }
            __syncthreads();
        }
        int sel = ri[0];
        if (sel < 0)    sel = 0;
        if (sel >= K_A) sel = K_A - 1;
        cnt1 += label[sel];
        if (tid == 0) kl[sel] = 1e300;
        __syncthreads();
    }
    // knn_cnt = [8-cnt1, cnt1]; argmax ties (4-4) -> class 0; output dtype is float32
    if (tid == 0) out[b] = (cnt1 > KNN / 2) ? 1.0f : 0.0f;
}

extern "C" void kernel_launch(void* const* d_in, const int* in_sizes, int n_in,
                              void* d_out, int out_size) {
    (void)in_sizes; (void)n_in; (void)out_size;
    const float* query  = (const float*)d_in[0];
    const float* anchor = (const float*)d_in[1];
    const int*   label  = (const int*)d_in[2];
    float* out = (float*)d_out;

    qlog_kernel<<<(B_Q * NPAIR + 255) / 256, 256>>>(query);
    dim3 g(K_A / KT, DSPLIT);
    gemm_kernel<<<g, 256>>>(anchor);
    topk_kernel<<<B_Q, 256>>>(label, out);
}

// round 6
// speedup vs baseline: 1.2305x; 1.2142x over previous
#include <cuda_runtime.h>
#include <cuda_bf16.h>
#include <cstdint>

#define D_DIM   50257
#define B_Q     64
#define K_A     4096
#define NPAIR   25129            // ceil(D/2); last pair has only .x valid
#define DSPLIT  18
#define PCHUNK  1397             // ceil(NPAIR/18)
#define KT      256
#define KTP     (KT + 2)         // +2 float2 pad: dp-stride 2064B kills bank conflicts
#define DP      8                // d-pairs per stage (16 d values)
#define EPSF    1e-10f
#define LN2F    0.69314718055994530942f
#define KNN     8

// ---- static device scratch (no cudaMalloc allowed) ----
__device__ float2 g_qlogP[NPAIR * B_Q];           // ~12.9 MB  (pair-major, b fast)
__device__ float  g_cross[DSPLIT * B_Q * K_A];    // ~18.9 MB  partial cross sums (ln units)
__device__ float  g_self [DSPLIT * K_A];          //  partial self sums (ln units)

// Packed dual-fp32 FMA (Blackwell f32x2 pipe): d = a*b + c on both lanes.
__device__ __forceinline__ float2 ffma2(float2 a, float2 b, float2 c) {
    unsigned long long ra = *reinterpret_cast<unsigned long long*>(&a);
    unsigned long long rb = *reinterpret_cast<unsigned long long*>(&b);
    unsigned long long rc = *reinterpret_cast<unsigned long long*>(&c);
    unsigned long long rd;
    asm("fma.rn.f32x2 %0, %1, %2, %3;" : "=l"(rd) : "l"(ra), "l"(rb), "l"(rc));
    return *reinterpret_cast<float2*>(&rd);
}

// ---------------- Kernel A: qlogP[p][b] = (ln(q[b][2p]+eps), ln(q[b][2p+1]+eps)) ----------------
__global__ void qlog_kernel(const float* __restrict__ q) {
    int idx = blockIdx.x * blockDim.x + threadIdx.x;
    if (idx >= B_Q * NPAIR) return;
    int b = idx / NPAIR;
    int p = idx % NPAIR;
    int d0 = 2 * p;
    float2 r;
    float x = q[(size_t)b * D_DIM + d0];
    r.x = __log2f(x + EPSF) * LN2F;
    r.y = 0.f;
    if (d0 + 1 < D_DIM) {
        float y = q[(size_t)b * D_DIM + d0 + 1];
        r.y = __log2f(y + EPSF) * LN2F;
    }
    g_qlogP[p * B_Q + b] = r;
}

// ---------------- Kernel B: fused cross-GEMM + self-term, coalesced loads + f32x2 FMA ----------------
__global__ void __launch_bounds__(256, 1)
gemm_kernel(const float* __restrict__ anchor) {
    __shared__ __align__(16) float2 As[2][DP][KTP];  // ~33 KB  (d-pair, local k, padded)
    __shared__ __align__(16) float2 Qs[2][DP][B_Q];  //   8 KB  (d-pair, b)

    const int tid = threadIdx.x;
    const int kb  = blockIdx.x * KT;
    const int c   = blockIdx.y;
    const int pstart = c * PCHUNK;
    const int pend   = min(pstart + PCHUNK, NPAIR);
    const int nst    = (pend - pstart + DP - 1) / DP;

    // compute mapping
    const int tx = tid & 31;          // k-lane: this thread's k elements are tx + 32*j
    const int ty = tid >> 5;          // warp id -> b group
    const int b0 = ty * 8;

    // load mapping: thread owns d-pair cp for rows rbase + 32*i  (coalesced within warp)
    const int cp    = tid & 7;        // which d-pair of the stage
    const int rbase = tid >> 3;       // 0..31

    const int qdp = tid >> 6;         // 0..3 ; loads d-pairs qdp and qdp+4
    const int qb  = tid & 63;

    float2 acc[8][8];                 // even-d / odd-d split accumulator chains
#pragma unroll
    for (int i = 0; i < 8; ++i)
#pragma unroll
        for (int j = 0; j < 8; ++j) acc[i][j] = make_float2(0.f, 0.f);

    float selfAcc[8];                 // per owned row (rbase + 32*i), this cp's d-pairs only
#pragma unroll
    for (int i = 0; i < 8; ++i) selfAcc[i] = 0.f;

    float2 va[8];
    float2 qv0, qv1;

    auto loadStage = [&](int s) {
        const int p0  = pstart + s * DP;
        const int pg  = p0 + cp;
        const bool pv = pg < pend;
        const int col = 2 * pg;
        const bool yok = pv && (col + 1 < D_DIM);
#pragma unroll
        for (int i = 0; i < 8; ++i) {
            const float* ap = anchor + (size_t)(kb + rbase + 32 * i) * D_DIM + col;
            float x = pv  ? __ldg(ap)     : 0.f;   // warp: 4 rows x 8 same-row floats -> ~6 wf/LDG
            float y = yok ? __ldg(ap + 1) : 0.f;
            va[i] = make_float2(x, y);
        }
        qv0 = (p0 + qdp     < pend) ? g_qlogP[(p0 + qdp    ) * B_Q + qb] : make_float2(0.f, 0.f);
        qv1 = (p0 + qdp + 4 < pend) ? g_qlogP[(p0 + qdp + 4) * B_Q + qb] : make_float2(0.f, 0.f);
    };

    auto storeStage = [&](int nb) {
#pragma unroll
        for (int i = 0; i < 8; ++i) {
            // self term: a * ln(a+eps); padded zeros contribute exactly 0
            selfAcc[i] += va[i].x * __log2f(va[i].x + EPSF)
                        + va[i].y * __log2f(va[i].y + EPSF);
            As[nb][cp][rbase + 32 * i] = va[i];
        }
        Qs[nb][qdp    ][qb] = qv0;
        Qs[nb][qdp + 4][qb] = qv1;
    };

    loadStage(0);
    storeStage(0);
    __syncthreads();

    int buf = 0;
    for (int s = 0; s < nst; ++s) {
        const bool more = (s + 1 < nst);
        if (more) loadStage(s + 1);   // next-stage global loads in flight across FMA section

#pragma unroll 2
        for (int dp = 0; dp < DP; ++dp) {
            float2 qf[8], af[8];
            const float4* qp = reinterpret_cast<const float4*>(&Qs[buf][dp][b0]); // warp-uniform bcast
#pragma unroll
            for (int h = 0; h < 4; ++h) {
                float4 t = qp[h];
                qf[2 * h]     = make_float2(t.x, t.y);
                qf[2 * h + 1] = make_float2(t.z, t.w);
            }
#pragma unroll
            for (int j = 0; j < 8; ++j)
                af[j] = As[buf][dp][tx + 32 * j];  // lanes consecutive: conflict-free LDS.64
#pragma unroll
            for (int i = 0; i < 8; ++i)
#pragma unroll
                for (int j = 0; j < 8; ++j)
                    acc[i][j] = ffma2(qf[i], af[j], acc[i][j]);   // 2 d-steps per instr
        }

        if (more) storeStage(buf ^ 1);
        __syncthreads();
        buf ^= 1;
    }

    // ---- epilogue: self-term reduce over the 8 cp-lanes sharing each row ----
#pragma unroll
    for (int i = 0; i < 8; ++i) {
        float s = selfAcc[i];
        s += __shfl_xor_sync(0xffffffffu, s, 1);
        s += __shfl_xor_sync(0xffffffffu, s, 2);
        s += __shfl_xor_sync(0xffffffffu, s, 4);
        if (cp == 0) g_self[c * K_A + kb + rbase + 32 * i] = s * LN2F;
    }
#pragma unroll
    for (int i = 0; i < 8; ++i) {
        float* dst = g_cross + ((size_t)(c * B_Q + b0 + i)) * K_A + kb;
#pragma unroll
        for (int j = 0; j < 8; ++j)
            dst[tx + 32 * j] = acc[i][j].x + acc[i][j].y;  // lanes consecutive: coalesced
    }
}

// ---------------- Kernel C: fp64 combine + top-8 argmin + majority vote ----------------
__global__ void __launch_bounds__(256)
topk_kernel(const int* __restrict__ label, float* __restrict__ out) {
    __shared__ double kl[K_A];     // 32 KB
    __shared__ double rv[256];
    __shared__ int    ri[256];
    const int b   = blockIdx.x;
    const int tid = threadIdx.x;

    for (int k = tid; k < K_A; k += 256) {
        double s = 0.0;
#pragma unroll
        for (int c = 0; c < DSPLIT; ++c)
            s += (double)g_self[c * K_A + k]
               - (double)g_cross[((size_t)(c * B_Q + b)) * K_A + k];
        kl[k] = s;   // = D * kl[b][k]; positive scaling is rank-invariant
    }
    __syncthreads();

    int cnt1 = 0;
    for (int r = 0; r < KNN; ++r) {
        double bv = 1e300; int bi = K_A - 1;
        for (int k = tid; k < K_A; k += 256) {
            double v = kl[k];
            if (v < bv) { bv = v; bi = k; }   // ascending k: lowest index wins ties (top_k semantics)
        }
        rv[tid] = bv; ri[tid] = bi;
        __syncthreads();
        for (int off = 128; off > 0; off >>= 1) {
            if (tid < off) {
                double v = rv[tid + off]; int i2 = ri[tid + off];
                if (v < rv[tid] || (v == rv[tid] && i2 < ri[tid])) { rv[tid] = v; ri[tid] = i2; }
            }
            __syncthreads();
        }
        int sel = ri[0];
        if (sel < 0)    sel = 0;
        if (sel >= K_A) sel = K_A - 1;
        cnt1 += label[sel];
        if (tid == 0) kl[sel] = 1e300;
        __syncthreads();
    }
    // knn_cnt = [8-cnt1, cnt1]; argmax ties (4-4) -> class 0; output dtype is float32
    if (tid == 0) out[b] = (cnt1 > KNN / 2) ? 1.0f : 0.0f;
}

extern "C" void kernel_launch(void* const* d_in, const int* in_sizes, int n_in,
                              void* d_out, int out_size) {
    (void)in_sizes; (void)n_in; (void)out_size;
    const float* query  = (const float*)d_in[0];
    const float* anchor = (const float*)d_in[1];
    const int*   label  = (const int*)d_in[2];
    float* out = (float*)d_out;

    qlog_kernel<<<(B_Q * NPAIR + 255) / 256, 256>>>(query);
    dim3 g(K_A / KT, DSPLIT);
    gemm_kernel<<<g, 256>>>(anchor);
    topk_kernel<<<B_Q, 256>>>(label, out);
}

// round 7
// speedup vs baseline: 1.3143x; 1.0681x over previous
#include <cuda_runtime.h>
#include <cuda_bf16.h>
#include <cstdint>

#define D_DIM   50257
#define B_Q     64
#define K_A     4096
#define NPAIR   25129            // ceil(D/2); last pair has only .x valid
#define DSPLIT  18
#define PCHUNK  1397             // ceil(NPAIR/18)
#define KT      256
#define KTP     (KT + 2)         // +2 float2 pad: dp-stride 2064B kills bank conflicts
#define DP      8                // d-pairs per stage (16 d values)
#define EPSF    1e-10f
#define LN2F    0.69314718055994530942f
#define KNN     8

// ---- static device scratch (no cudaMalloc allowed) ----
__device__ float2 g_qlogP[NPAIR * B_Q];           // ~12.9 MB  (pair-major, b fast)
__device__ float  g_cross[DSPLIT * B_Q * K_A];    // ~18.9 MB  partial cross sums (ln units)
__device__ float  g_self [DSPLIT * K_A];          //  partial self sums (ln units)

// Packed dual-fp32 FMA (Blackwell f32x2 pipe): d = a*b + c on both lanes.
__device__ __forceinline__ float2 ffma2(float2 a, float2 b, float2 c) {
    unsigned long long ra = *reinterpret_cast<unsigned long long*>(&a);
    unsigned long long rb = *reinterpret_cast<unsigned long long*>(&b);
    unsigned long long rc = *reinterpret_cast<unsigned long long*>(&c);
    unsigned long long rd;
    asm("fma.rn.f32x2 %0, %1, %2, %3;" : "=l"(rd) : "l"(ra), "l"(rb), "l"(rc));
    return *reinterpret_cast<float2*>(&rd);
}

// ---------------- Kernel A: qlogP[p][b] = (ln(q[b][2p]+eps), ln(q[b][2p+1]+eps)) ----------------
__global__ void qlog_kernel(const float* __restrict__ q) {
    int idx = blockIdx.x * blockDim.x + threadIdx.x;
    if (idx >= B_Q * NPAIR) return;
    int b = idx / NPAIR;
    int p = idx % NPAIR;
    int d0 = 2 * p;
    float2 r;
    float x = q[(size_t)b * D_DIM + d0];
    r.x = __log2f(x + EPSF) * LN2F;
    r.y = 0.f;
    if (d0 + 1 < D_DIM) {
        float y = q[(size_t)b * D_DIM + d0 + 1];
        r.y = __log2f(y + EPSF) * LN2F;
    }
    g_qlogP[p * B_Q + b] = r;
}

// ---------------- Kernel B: fused cross-GEMM + self-term ----------------
// Loader: lg = tid&15 -> one of 16 CONSECUTIVE floats (8 d-pairs); rg = tid>>4 -> row group.
// Each scalar LDG: warp covers 2 rows x 64 contiguous bytes -> ~2-4 lines (vs ~6 before).
__global__ void __launch_bounds__(256, 1)
gemm_kernel(const float* __restrict__ anchor) {
    __shared__ __align__(16) float2 As[2][DP][KTP];  // ~33 KB  (d-pair, local k, padded)
    __shared__ __align__(16) float2 Qs[2][DP][B_Q];  //   8 KB  (d-pair, b)

    const int tid = threadIdx.x;
    const int kb  = blockIdx.x * KT;
    const int c   = blockIdx.y;
    const int pstart = c * PCHUNK;
    const int pend   = min(pstart + PCHUNK, NPAIR);
    const int nst    = (pend - pstart + DP - 1) / DP;

    // compute mapping (unchanged from round 6)
    const int tx = tid & 31;          // k-lane: this thread's k elements are tx + 32*j
    const int ty = tid >> 5;          // warp id -> b group
    const int b0 = ty * 8;

    // loader mapping: contiguous-float scheme
    const int lg = tid & 15;          // which of 16 consecutive floats (d-pair lg>>1, comp lg&1)
    const int rg = tid >> 4;          // 0..15; thread's rows are rg + 16*m

    const int qdp = tid >> 6;         // 0..3 ; loads d-pairs qdp and qdp+4
    const int qb  = tid & 63;

    float2 acc[8][8];                 // even-d / odd-d split accumulator chains
#pragma unroll
    for (int i = 0; i < 8; ++i)
#pragma unroll
        for (int j = 0; j < 8; ++j) acc[i][j] = make_float2(0.f, 0.f);

    float selfAcc[16];                // per owned row (rg + 16*m), this lg-float only
#pragma unroll
    for (int m = 0; m < 16; ++m) selfAcc[m] = 0.f;

    float  va[16];
    float2 qv0, qv1;

    auto loadStage = [&](int s) {
        const int p0 = pstart + s * DP;
        const int pg = p0 + (lg >> 1);
        // valid unless d-pair out of chunk, or odd component of the final (odd-D) pair
        const bool valid = (pg < pend) && !((lg & 1) && (2 * pg + 1 >= D_DIM));
        const int colf = 2 * p0 + lg;
#pragma unroll
        for (int m = 0; m < 16; ++m) {
            const float* ap = anchor + (size_t)(kb + rg + 16 * m) * D_DIM + colf;
            va[m] = valid ? __ldg(ap) : 0.f;   // warp: 2 rows x 64B contiguous per LDG
        }
        qv0 = (p0 + qdp     < pend) ? g_qlogP[(p0 + qdp    ) * B_Q + qb] : make_float2(0.f, 0.f);
        qv1 = (p0 + qdp + 4 < pend) ? g_qlogP[(p0 + qdp + 4) * B_Q + qb] : make_float2(0.f, 0.f);
    };

    auto storeStage = [&](int nb) {
        float* asbase = reinterpret_cast<float*>(&As[nb][lg >> 1][0]) + (lg & 1);
#pragma unroll
        for (int m = 0; m < 16; ++m) {
            // self term: a * ln(a+eps); padded zeros contribute exactly 0
            selfAcc[m] += va[m] * __log2f(va[m] + EPSF);
            asbase[2 * (rg + 16 * m)] = va[m];   // conflict-free STS.32 (proven bank map)
        }
        Qs[nb][qdp    ][qb] = qv0;
        Qs[nb][qdp + 4][qb] = qv1;
    };

    loadStage(0);
    storeStage(0);
    __syncthreads();

    int buf = 0;
    for (int s = 0; s < nst; ++s) {
        const bool more = (s + 1 < nst);
        if (more) loadStage(s + 1);   // next-stage global loads in flight across FMA section

#pragma unroll 2
        for (int dp = 0; dp < DP; ++dp) {
            float2 qf[8], af[8];
            const float4* qp = reinterpret_cast<const float4*>(&Qs[buf][dp][b0]); // warp-uniform bcast
#pragma unroll
            for (int h = 0; h < 4; ++h) {
                float4 t = qp[h];
                qf[2 * h]     = make_float2(t.x, t.y);
                qf[2 * h + 1] = make_float2(t.z, t.w);
            }
#pragma unroll
            for (int j = 0; j < 8; ++j)
                af[j] = As[buf][dp][tx + 32 * j];  // lanes consecutive: conflict-free LDS.64
#pragma unroll
            for (int i = 0; i < 8; ++i)
#pragma unroll
                for (int j = 0; j < 8; ++j)
                    acc[i][j] = ffma2(qf[i], af[j], acc[i][j]);   // 2 d-steps per instr
        }

        if (more) storeStage(buf ^ 1);
        __syncthreads();
        buf ^= 1;
    }

    // ---- epilogue: self-term reduce over the 16 lg-lanes sharing each row ----
#pragma unroll
    for (int m = 0; m < 16; ++m) {
        float s = selfAcc[m];
        s += __shfl_xor_sync(0xffffffffu, s, 1);
        s += __shfl_xor_sync(0xffffffffu, s, 2);
        s += __shfl_xor_sync(0xffffffffu, s, 4);
        s += __shfl_xor_sync(0xffffffffu, s, 8);
        if (lg == 0) g_self[c * K_A + kb + rg + 16 * m] = s * LN2F;
    }
#pragma unroll
    for (int i = 0; i < 8; ++i) {
        float* dst = g_cross + ((size_t)(c * B_Q + b0 + i)) * K_A + kb;
#pragma unroll
        for (int j = 0; j < 8; ++j)
            dst[tx + 32 * j] = acc[i][j].x + acc[i][j].y;  // lanes consecutive: coalesced
    }
}

// ---------------- Kernel C: fp64 combine + top-8 argmin + majority vote ----------------
__global__ void __launch_bounds__(256)
topk_kernel(const int* __restrict__ label, float* __restrict__ out) {
    __shared__ double kl[K_A];     // 32 KB
    __shared__ double rv[256];
    __shared__ int    ri[256];
    const int b   = blockIdx.x;
    const int tid = threadIdx.x;

    for (int k = tid; k < K_A; k += 256) {
        double s = 0.0;
#pragma unroll
        for (int c = 0; c < DSPLIT; ++c)
            s += (double)g_self[c * K_A + k]
               - (double)g_cross[((size_t)(c * B_Q + b)) * K_A + k];
        kl[k] = s;   // = D * kl[b][k]; positive scaling is rank-invariant
    }
    __syncthreads();

    int cnt1 = 0;
    for (int r = 0; r < KNN; ++r) {
        double bv = 1e300; int bi = K_A - 1;
        for (int k = tid; k < K_A; k += 256) {
            double v = kl[k];
            if (v < bv) { bv = v; bi = k; }   // ascending k: lowest index wins ties (top_k semantics)
        }
        rv[tid] = bv; ri[tid] = bi;
        __syncthreads();
        for (int off = 128; off > 0; off >>= 1) {
            if (tid < off) {
                double v = rv[tid + off]; int i2 = ri[tid + off];
                if (v < rv[tid] || (v == rv[tid] && i2 < ri[tid])) { rv[tid] = v; ri[tid] = i2; }
            }
            __syncthreads();
        }
        int sel = ri[0];
        if (sel < 0)    sel = 0;
        if (sel >= K_A) sel = K_A - 1;
        cnt1 += label[sel];
        if (tid == 0) kl[sel] = 1e300;
        __syncthreads();
    }
    // knn_cnt = [8-cnt1, cnt1]; argmax ties (4-4) -> class 0; output dtype is float32
    if (tid == 0) out[b] = (cnt1 > KNN / 2) ? 1.0f : 0.0f;
}

extern "C" void kernel_launch(void* const* d_in, const int* in_sizes, int n_in,
                              void* d_out, int out_size) {
    (void)in_sizes; (void)n_in; (void)out_size;
    const float* query  = (const float*)d_in[0];
    const float* anchor = (const float*)d_in[1];
    const int*   label  = (const int*)d_in[2];
    float* out = (float*)d_out;

    qlog_kernel<<<(B_Q * NPAIR + 255) / 256, 256>>>(query);
    dim3 g(K_A / KT, DSPLIT);
    gemm_kernel<<<g, 256>>>(anchor);
    topk_kernel<<<B_Q, 256>>>(label, out);
}